// round 2
// baseline (speedup 1.0000x reference)
#include <cuda_runtime.h>

// 81 multilinear coefficients: ev = sum_{t in {1,C,S}^4} K[t] * prod_q e_q(t_q)
__device__ float g_K[81];

// ---------------------------------------------------------------------------
// Setup: build U (16x16) from weights, M = Re(U^dag Z0 U), project to K[81].
// One block of 256 threads; threads 0..15 each simulate one basis column.
// ---------------------------------------------------------------------------
__global__ void qcl_setup_kernel(const float* __restrict__ w) {
    __shared__ float sUr[16][16];   // [row k][col j]
    __shared__ float sUi[16][16];
    __shared__ float sM[16][16];

    const int tid = threadIdx.x;

    if (tid < 16) {
        // column j = circuit applied to basis state e_j
        float ar[16], ai[16];
        #pragma unroll
        for (int k = 0; k < 16; k++) { ar[k] = (k == tid) ? 1.f : 0.f; ai[k] = 0.f; }

        // complex 2x2 gate on wire q (bit mask m = 8>>q, wire 0 = MSB)
        auto apply = [&](int q,
                         float g00r, float g00i, float g01r, float g01i,
                         float g10r, float g10i, float g11r, float g11i) {
            int m = 8 >> q;
            for (int k = 0; k < 16; k++) {
                if (k & m) continue;
                int k1 = k | m;
                float a0r = ar[k],  a0i = ai[k];
                float a1r = ar[k1], a1i = ai[k1];
                ar[k]  = g00r * a0r - g00i * a0i + g01r * a1r - g01i * a1i;
                ai[k]  = g00r * a0i + g00i * a0r + g01r * a1i + g01i * a1r;
                ar[k1] = g10r * a0r - g10i * a0i + g11r * a1r - g11i * a1i;
                ai[k1] = g10r * a0i + g10i * a0r + g11r * a1i + g11i * a1r;
            }
        };
        // CNOT: control mask mc, target mask mt
        auto cnot = [&](int mc, int mt) {
            for (int k = 0; k < 16; k++) {
                if ((k & mc) && !(k & mt)) {
                    int k1 = k | mt;
                    float tr = ar[k]; ar[k] = ar[k1]; ar[k1] = tr;
                    float ti = ai[k]; ai[k] = ai[k1]; ai[k1] = ti;
                }
            }
        };

        for (int layer = 0; layer < 2; layer++) {
            for (int q = 0; q < 4; q++) {
                const float* wq = w + (layer * 4 + q) * 3;
                float c, s;
                // RX(theta): [[c, -i s], [-i s, c]]
                c = cosf(wq[0] * 0.5f); s = sinf(wq[0] * 0.5f);
                apply(q, c, 0.f, 0.f, -s, 0.f, -s, c, 0.f);
                // RY(theta): [[c, -s], [s, c]]
                c = cosf(wq[1] * 0.5f); s = sinf(wq[1] * 0.5f);
                apply(q, c, 0.f, -s, 0.f, s, 0.f, c, 0.f);
                // RZ(theta): diag(e^{-i t/2}, e^{+i t/2})
                c = cosf(wq[2] * 0.5f); s = sinf(wq[2] * 0.5f);
                apply(q, c, -s, 0.f, 0.f, 0.f, 0.f, c, s);
            }
            // CNOT(0,1), CNOT(2,3), CNOT(0,2), CNOT(1,3)  (wire q -> mask 8>>q)
            cnot(8, 4);
            cnot(2, 1);
            cnot(8, 2);
            cnot(4, 1);
        }

        #pragma unroll
        for (int k = 0; k < 16; k++) { sUr[k][tid] = ar[k]; sUi[k][tid] = ai[k]; }
    }
    __syncthreads();

    // M[i][j] = Re( sum_k z_k * conj(U[k][i]) * U[k][j] ),  z_k = (k&8) ? -1 : +1
    {
        int i = tid >> 4, j = tid & 15;
        float acc = 0.f;
        #pragma unroll
        for (int k = 0; k < 16; k++) {
            float z = (k & 8) ? -1.f : 1.f;
            acc += z * (sUr[k][i] * sUr[k][j] + sUi[k][i] * sUi[k][j]);
        }
        sM[i][j] = acc;
    }
    __syncthreads();

    // Project symmetric M onto per-wire basis {1, cos, sin}:
    //   c^2 = (1+C)/2, s^2 = (1-C)/2, c*s = S/2   (c,s at half-angle; C,S full angle)
    if (tid < 81) {
        int t3 = tid % 3, t2 = (tid / 3) % 3, t1 = (tid / 9) % 3, t0 = tid / 27;
        const float W[3][2][2] = {
            { {0.5f, 0.0f}, {0.0f,  0.5f} },   // constant part
            { {0.5f, 0.0f}, {0.0f, -0.5f} },   // cos part
            { {0.0f, 0.5f}, {0.5f,  0.0f} },   // sin part
        };
        float acc = 0.f;
        for (int i = 0; i < 16; i++) {
            for (int j = 0; j < 16; j++) {
                float wg = W[t0][(i >> 3) & 1][(j >> 3) & 1]
                         * W[t1][(i >> 2) & 1][(j >> 2) & 1]
                         * W[t2][(i >> 1) & 1][(j >> 1) & 1]
                         * W[t3][ i       & 1][ j       & 1];
                acc += wg * sM[i][j];
            }
        }
        g_K[tid] = acc;
    }
}

// ---------------------------------------------------------------------------
// Main: one thread per output pixel. 4 loads, 4 fast sincos, 80-FMA contraction.
// ---------------------------------------------------------------------------
__global__ void __launch_bounds__(256)
qcl_main_kernel(const float* __restrict__ x, float* __restrict__ out, int total) {
    __shared__ float Ks[81];
    if (threadIdx.x < 81) Ks[threadIdx.x] = g_K[threadIdx.x];
    __syncthreads();

    int idx = blockIdx.x * blockDim.x + threadIdx.x;
    if (idx >= total) return;

    // output layout: [plane][127][127], input: [plane][128][128]
    int p    = idx / 16129;            // 127*127
    int rem  = idx - p * 16129;
    int h    = rem / 127;
    int wcol = rem - h * 127;

    const float* xp = x + p * 16384 + h * 128 + wcol;
    float x00 = __ldg(xp + 0);     // wire 0 (top-left)
    float x01 = __ldg(xp + 1);     // wire 1 (top-right)
    float x10 = __ldg(xp + 128);   // wire 2 (bottom-left)
    float x11 = __ldg(xp + 129);   // wire 3 (bottom-right)

    // inputs ~N(0,1): MUFU-based fast sincos is accurate to ~1e-6 abs here
    float C0, S0, C1, S1, C2, S2, C3, S3;
    __sincosf(x00, &S0, &C0);
    __sincosf(x01, &S1, &C1);
    __sincosf(x10, &S2, &C2);
    __sincosf(x11, &S3, &C3);

    // nested contraction: t3 (innermost) -> t2 -> t1 -> t0
    float r3[27];
    #pragma unroll
    for (int a = 0; a < 27; a++)
        r3[a] = fmaf(Ks[a * 3 + 1], C3, fmaf(Ks[a * 3 + 2], S3, Ks[a * 3 + 0]));

    float r2[9];
    #pragma unroll
    for (int a = 0; a < 9; a++)
        r2[a] = fmaf(r3[a * 3 + 1], C2, fmaf(r3[a * 3 + 2], S2, r3[a * 3 + 0]));

    float r1a = fmaf(r2[1], C1, fmaf(r2[2], S1, r2[0]));
    float r1b = fmaf(r2[4], C1, fmaf(r2[5], S1, r2[3]));
    float r1c = fmaf(r2[7], C1, fmaf(r2[8], S1, r2[6]));

    out[idx] = fmaf(r1b, C0, fmaf(r1c, S0, r1a));
}

extern "C" void kernel_launch(void* const* d_in, const int* in_sizes, int n_in,
                              void* d_out, int out_size) {
    const float* x = (const float*)d_in[0];   // [32,3,128,128]
    const float* w = (const float*)d_in[1];   // [2,4,3]
    float* out = (float*)d_out;               // [32,3,127,127]

    qcl_setup_kernel<<<1, 256>>>(w);

    int total  = out_size;                    // 32*3*127*127
    int blocks = (total + 255) / 256;
    qcl_main_kernel<<<blocks, 256>>>(x, out, total);
}

// round 3
// speedup vs baseline: 1.0803x; 1.0803x over previous
#include <cuda_runtime.h>

// K split by t3: g_Ks[t3*27 + (t0*9 + t1*3 + t2)]
__device__ float g_Ks[81];

// ---------------------------------------------------------------------------
// Setup: build U (16x16) from weights, M = Re(U^dag Z0 U), project to K[81].
// One block of 256 threads.
// ---------------------------------------------------------------------------
__global__ void qcl_setup_kernel(const float* __restrict__ w) {
    __shared__ float sUr[16][16];   // [row k][col j]
    __shared__ float sUi[16][16];
    __shared__ float sM[16][16];
    __shared__ float gc[24], gs[24];

    const int tid = threadIdx.x;

    // parallel transcendentals for all 24 rotation params
    if (tid < 24) {
        gc[tid] = cosf(w[tid] * 0.5f);
        gs[tid] = sinf(w[tid] * 0.5f);
    }
    __syncthreads();

    if (tid < 16) {
        // column j = circuit applied to basis state e_j
        float ar[16], ai[16];
        #pragma unroll
        for (int k = 0; k < 16; k++) { ar[k] = (k == tid) ? 1.f : 0.f; ai[k] = 0.f; }

        // complex 2x2 gate on wire q (bit mask m = 8>>q, wire 0 = MSB)
        auto apply = [&](int q,
                         float g00r, float g00i, float g01r, float g01i,
                         float g10r, float g10i, float g11r, float g11i) {
            int m = 8 >> q;
            for (int k = 0; k < 16; k++) {
                if (k & m) continue;
                int k1 = k | m;
                float a0r = ar[k],  a0i = ai[k];
                float a1r = ar[k1], a1i = ai[k1];
                ar[k]  = g00r * a0r - g00i * a0i + g01r * a1r - g01i * a1i;
                ai[k]  = g00r * a0i + g00i * a0r + g01r * a1i + g01i * a1r;
                ar[k1] = g10r * a0r - g10i * a0i + g11r * a1r - g11i * a1i;
                ai[k1] = g10r * a0i + g10i * a0r + g11r * a1i + g11i * a1r;
            }
        };
        auto cnot = [&](int mc, int mt) {
            for (int k = 0; k < 16; k++) {
                if ((k & mc) && !(k & mt)) {
                    int k1 = k | mt;
                    float tr = ar[k]; ar[k] = ar[k1]; ar[k1] = tr;
                    float ti = ai[k]; ai[k] = ai[k1]; ai[k1] = ti;
                }
            }
        };

        for (int layer = 0; layer < 2; layer++) {
            for (int q = 0; q < 4; q++) {
                int base = (layer * 4 + q) * 3;
                float c, s;
                // RX: [[c, -i s], [-i s, c]]
                c = gc[base + 0]; s = gs[base + 0];
                apply(q, c, 0.f, 0.f, -s, 0.f, -s, c, 0.f);
                // RY: [[c, -s], [s, c]]
                c = gc[base + 1]; s = gs[base + 1];
                apply(q, c, 0.f, -s, 0.f, s, 0.f, c, 0.f);
                // RZ: diag(e^{-i t/2}, e^{+i t/2})
                c = gc[base + 2]; s = gs[base + 2];
                apply(q, c, -s, 0.f, 0.f, 0.f, 0.f, c, s);
            }
            // CNOT(0,1), CNOT(2,3), CNOT(0,2), CNOT(1,3) (wire q -> mask 8>>q)
            cnot(8, 4);
            cnot(2, 1);
            cnot(8, 2);
            cnot(4, 1);
        }

        #pragma unroll
        for (int k = 0; k < 16; k++) { sUr[k][tid] = ar[k]; sUi[k][tid] = ai[k]; }
    }
    __syncthreads();

    // M[i][j] = Re( sum_k z_k * conj(U[k][i]) * U[k][j] ),  z_k = (k&8) ? -1 : +1
    {
        int i = tid >> 4, j = tid & 15;
        float acc = 0.f;
        #pragma unroll
        for (int k = 0; k < 16; k++) {
            float z = (k & 8) ? -1.f : 1.f;
            acc += z * (sUr[k][i] * sUr[k][j] + sUi[k][i] * sUi[k][j]);
        }
        sM[i][j] = acc;
    }
    __syncthreads();

    // Project symmetric M onto per-wire basis {1, cos, sin}:
    //   c^2=(1+C)/2, s^2=(1-C)/2, c*s=S/2 (c,s half-angle; C,S full angle)
    // Per-wire 2x2 weights held in registers (no local-memory indexing).
    if (tid < 81) {
        int t3 = tid % 3, t2 = (tid / 3) % 3, t1 = (tid / 9) % 3, t0 = tid / 27;
        auto mkw = [](int t, float& w00, float& w01, float& w10, float& w11) {
            w00 = (t == 2) ? 0.f : 0.5f;
            w11 = (t == 0) ? 0.5f : ((t == 1) ? -0.5f : 0.f);
            w01 = (t == 2) ? 0.5f : 0.f;
            w10 = w01;
        };
        float a00, a01, a10, a11;  mkw(t0, a00, a01, a10, a11);
        float b00, b01, b10, b11;  mkw(t1, b00, b01, b10, b11);
        float c00, c01, c10, c11;  mkw(t2, c00, c01, c10, c11);
        float d00, d01, d10, d11;  mkw(t3, d00, d01, d10, d11);

        float acc = 0.f;
        #pragma unroll 4
        for (int i = 0; i < 16; i++) {
            #pragma unroll 4
            for (int j = 0; j < 16; j++) {
                float f0 = (i & 8) ? ((j & 8) ? a11 : a10) : ((j & 8) ? a01 : a00);
                float f1 = (i & 4) ? ((j & 4) ? b11 : b10) : ((j & 4) ? b01 : b00);
                float f2 = (i & 2) ? ((j & 2) ? c11 : c10) : ((j & 2) ? c01 : c00);
                float f3 = (i & 1) ? ((j & 1) ? d11 : d10) : ((j & 1) ? d01 : d00);
                acc = fmaf(f0 * f1, f2 * f3 * sM[i][j], acc);
            }
        }
        // split-by-t3 layout for vectorized LDS in main kernel
        g_Ks[t3 * 27 + (t0 * 9 + t1 * 3 + t2)] = acc;
    }
}

// ---------------------------------------------------------------------------
// Main: one thread per 4-pixel strip. 5 columns of sincos shared across the
// strip; contraction reads K via float4 shared loads (21 LDS.128 / pixel).
// ---------------------------------------------------------------------------
__global__ void __launch_bounds__(256)
qcl_main_kernel(const float* __restrict__ x, float* __restrict__ out, int nStrips) {
    __shared__ __align__(16) float sK[3 * 28];   // each 27-part padded to 28
    if (threadIdx.x < 84) {
        int part = threadIdx.x / 28, idx = threadIdx.x - part * 28;
        sK[threadIdx.x] = (idx < 27) ? g_Ks[part * 27 + idx] : 0.f;
    }
    __syncthreads();
    const float4* sK4 = (const float4*)sK;       // sK4[part*7 + v]

    int sid = blockIdx.x * blockDim.x + threadIdx.x;
    if (sid >= nStrips) return;

    // strips: 32 per row (last covers 3 pixels), 127 rows, 96 planes
    int p    = sid / 4064;            // 127*32
    int rem  = sid - p * 4064;
    int h    = rem >> 5;
    int w0   = (rem & 31) << 2;       // 0..124, 16B-aligned
    bool full = (w0 < 124);
    int npix  = full ? 4 : 3;

    const float* r0 = x + p * 16384 + h * 128 + w0;
    float4 t4 = *(const float4*)r0;
    float4 b4 = *(const float4*)(r0 + 128);
    float  t5 = full ? __ldg(r0 + 4)   : 0.f;
    float  b5 = full ? __ldg(r0 + 132) : 0.f;

    float Ct[5], St[5], Cb[5], Sb[5];
    __sincosf(t4.x, &St[0], &Ct[0]);  __sincosf(b4.x, &Sb[0], &Cb[0]);
    __sincosf(t4.y, &St[1], &Ct[1]);  __sincosf(b4.y, &Sb[1], &Cb[1]);
    __sincosf(t4.z, &St[2], &Ct[2]);  __sincosf(b4.z, &Sb[2], &Cb[2]);
    __sincosf(t4.w, &St[3], &Ct[3]);  __sincosf(b4.w, &Sb[3], &Cb[3]);
    __sincosf(t5,   &St[4], &Ct[4]);  __sincosf(b5,   &Sb[4], &Cb[4]);

    float* o = out + p * 16129 + h * 127 + w0;

    #pragma unroll
    for (int k = 0; k < 4; k++) {
        // wires: 0=top-left, 1=top-right, 2=bottom-left, 3=bottom-right
        float C0 = Ct[k],     S0 = St[k];
        float C1 = Ct[k + 1], S1 = St[k + 1];
        float C2 = Cb[k],     S2 = Sb[k];
        float C3 = Cb[k + 1], S3 = Sb[k + 1];

        // level t3: r[a] = K0[a] + K1[a]*C3 + K2[a]*S3, a = t0*9+t1*3+t2
        float r[28];
        #pragma unroll
        for (int v = 0; v < 7; v++) {
            float4 k0 = sK4[v], k1 = sK4[7 + v], k2 = sK4[14 + v];
            r[4 * v + 0] = fmaf(k1.x, C3, fmaf(k2.x, S3, k0.x));
            r[4 * v + 1] = fmaf(k1.y, C3, fmaf(k2.y, S3, k0.y));
            r[4 * v + 2] = fmaf(k1.z, C3, fmaf(k2.z, S3, k0.z));
            r[4 * v + 3] = fmaf(k1.w, C3, fmaf(k2.w, S3, k0.w));
        }

        // level t2
        float r2[9];
        #pragma unroll
        for (int a = 0; a < 9; a++)
            r2[a] = fmaf(r[3 * a + 1], C2, fmaf(r[3 * a + 2], S2, r[3 * a]));

        // levels t1, t0
        float ra = fmaf(r2[1], C1, fmaf(r2[2], S1, r2[0]));
        float rb = fmaf(r2[4], C1, fmaf(r2[5], S1, r2[3]));
        float rc = fmaf(r2[7], C1, fmaf(r2[8], S1, r2[6]));
        float ev = fmaf(rb, C0, fmaf(rc, S0, ra));

        if (k < npix) o[k] = ev;
    }
}

extern "C" void kernel_launch(void* const* d_in, const int* in_sizes, int n_in,
                              void* d_out, int out_size) {
    const float* x = (const float*)d_in[0];   // [32,3,128,128]
    const float* w = (const float*)d_in[1];   // [2,4,3]
    float* out = (float*)d_out;               // [32,3,127,127]

    qcl_setup_kernel<<<1, 256>>>(w);

    const int nStrips = 96 * 127 * 32;        // 390144
    const int blocks  = (nStrips + 255) / 256; // 1524
    qcl_main_kernel<<<blocks, 256>>>(x, out, nStrips);
}

// round 4
// speedup vs baseline: 1.8889x; 1.7485x over previous
#include <cuda_runtime.h>

// ---------------------------------------------------------------------------
// Fully fused kernel. Prologue (per block, redundant): build U (16x16) from
// weights via a lane-parallel shuffle simulator, M = Re(U^dag Z0 U), sparse
// projection to 81 multilinear coefficients K. Main phase: persistent
// grid-stride over 4-pixel strips.
//   ev = sum_{t in {1,C,S}^4} K[t] * prod_q e_q(t_q)
// ---------------------------------------------------------------------------
__global__ void __launch_bounds__(256)
qcl_fused_kernel(const float* __restrict__ x, const float* __restrict__ w,
                 float* __restrict__ out, int nStrips) {
    __shared__ float sUr[16][17];
    __shared__ float sUi[16][17];
    __shared__ float sM[16][17];
    __shared__ float sgc[24], sgs[24];
    __shared__ __align__(16) float sK[3 * 28];   // split by t3, each 27 padded to 28

    const int tid = threadIdx.x;

    // ---- weights' half-angle sincos (precise; done once) ----
    if (tid < 24) {
        sgc[tid] = cosf(w[tid] * 0.5f);
        sgs[tid] = sinf(w[tid] * 0.5f);
    }
    __syncthreads();

    // ---- shuffle simulator: thread owns amplitude kk of column col ----
    // 256 threads = 8 warps x (2 columns x 16 amplitudes). Wire q -> mask 8>>q,
    // masks < 16 so shfl_xor stays within each 16-lane half (distinct columns).
    {
        const int lane = tid & 31;
        const int kk   = lane & 15;
        const int col  = ((tid >> 5) << 1) | (lane >> 4);

        float ar = (kk == col) ? 1.f : 0.f;
        float ai = 0.f;

        // generic complex 2x2 gate on wire mask m
        auto rot = [&](int m, float g00r, float g00i, float g01r, float g01i,
                              float g10r, float g10i, float g11r, float g11i) {
            float pr = __shfl_xor_sync(0xffffffffu, ar, m);
            float pi = __shfl_xor_sync(0xffffffffu, ai, m);
            bool  b  = (kk & m) != 0;
            float ur = b ? pr : ar, ui = b ? pi : ai;   // bit-clear amplitude
            float wr = b ? ar : pr, wi = b ? ai : pi;   // bit-set amplitude
            float c0r = b ? g10r : g00r, c0i = b ? g10i : g00i;
            float c1r = b ? g11r : g01r, c1i = b ? g11i : g01i;
            ar = c0r * ur - c0i * ui + c1r * wr - c1i * wi;
            ai = c0r * ui + c0i * ur + c1r * wi + c1i * wr;
        };
        auto cnot = [&](int mc, int mt) {
            float pr = __shfl_xor_sync(0xffffffffu, ar, mt);
            float pi = __shfl_xor_sync(0xffffffffu, ai, mt);
            if (kk & mc) { ar = pr; ai = pi; }
        };

        #pragma unroll
        for (int g8 = 0; g8 < 8; g8++) {     // layer*4 + q
            int q = g8 & 3;
            int m = 8 >> q;
            int base = g8 * 3;
            float c, s;
            c = sgc[base + 0]; s = sgs[base + 0];          // RX: [[c,-is],[-is,c]]
            rot(m, c, 0.f, 0.f, -s, 0.f, -s, c, 0.f);
            c = sgc[base + 1]; s = sgs[base + 1];          // RY: [[c,-s],[s,c]]
            rot(m, c, 0.f, -s, 0.f, s, 0.f, c, 0.f);
            c = sgc[base + 2]; s = sgs[base + 2];          // RZ: diag(e^-it/2, e^it/2)
            rot(m, c, -s, 0.f, 0.f, 0.f, 0.f, c, s);
            if (q == 3) {                                  // entangler after each layer
                cnot(8, 4); cnot(2, 1); cnot(8, 2); cnot(4, 1);
            }
        }

        sUr[kk][col] = ar;
        sUi[kk][col] = ai;
    }
    __syncthreads();

    // ---- M[i][j] = Re(sum_k z_k conj(U[k][i]) U[k][j]), z_k = (k&8)?-1:+1 ----
    {
        int i = tid >> 4, j = tid & 15;
        float acc = 0.f;
        #pragma unroll
        for (int k = 0; k < 16; k++) {
            float z = (k & 8) ? -1.f : 1.f;
            acc += z * (sUr[k][i] * sUr[k][j] + sUi[k][i] * sUi[k][j]);
        }
        sM[i][j] = acc;
    }
    __syncthreads();

    // ---- sparse projection: each per-wire weight matrix has 2 nonzeros ----
    // K[t] = (1/16) sum_{c=0..15} (-1)^popc(c & smask) * M[c][c ^ xmask]
    //   xmask bit(3-q) set iff t_q==2 (sin term), smask bit(3-q) set iff t_q==1
    if (tid < 81) {
        int t3 = tid % 3, r = tid / 3;
        int t2 = r % 3;  r /= 3;
        int t1 = r % 3;
        int t0 = r / 3;
        int xmask = ((t0 == 2) << 3) | ((t1 == 2) << 2) | ((t2 == 2) << 1) | (t3 == 2);
        int smask = ((t0 == 1) << 3) | ((t1 == 1) << 2) | ((t2 == 1) << 1) | (t3 == 1);
        float acc = 0.f;
        #pragma unroll
        for (int c = 0; c < 16; c++) {
            float sgn = (__popc(c & smask) & 1) ? -1.f : 1.f;
            acc += sgn * sM[c][c ^ xmask];
        }
        sK[t3 * 28 + (t0 * 9 + t1 * 3 + t2)] = acc * 0.0625f;
    }
    if (tid >= 81 && tid < 84) sK[(tid - 81) * 28 + 27] = 0.f;   // pad slots
    __syncthreads();

    const float4* sK4 = (const float4*)sK;       // sK4[part*7 + v]

    // ---- main phase: persistent grid-stride over 4-pixel strips ----
    const int stride = gridDim.x * blockDim.x;
    for (int sid = blockIdx.x * blockDim.x + tid; sid < nStrips; sid += stride) {
        // strips: 32 per row (last covers 3 pixels), 127 rows, 96 planes
        int p    = sid / 4064;            // 127*32
        int rem  = sid - p * 4064;
        int h    = rem >> 5;
        int w0   = (rem & 31) << 2;       // 0..124, 16B-aligned
        bool full = (w0 < 124);
        int npix  = full ? 4 : 3;

        const float* r0 = x + p * 16384 + h * 128 + w0;
        float4 t4 = *(const float4*)r0;
        float4 b4 = *(const float4*)(r0 + 128);
        float  t5 = full ? __ldg(r0 + 4)   : 0.f;
        float  b5 = full ? __ldg(r0 + 132) : 0.f;

        float Ct[5], St[5], Cb[5], Sb[5];
        __sincosf(t4.x, &St[0], &Ct[0]);  __sincosf(b4.x, &Sb[0], &Cb[0]);
        __sincosf(t4.y, &St[1], &Ct[1]);  __sincosf(b4.y, &Sb[1], &Cb[1]);
        __sincosf(t4.z, &St[2], &Ct[2]);  __sincosf(b4.z, &Sb[2], &Cb[2]);
        __sincosf(t4.w, &St[3], &Ct[3]);  __sincosf(b4.w, &Sb[3], &Cb[3]);
        __sincosf(t5,   &St[4], &Ct[4]);  __sincosf(b5,   &Sb[4], &Cb[4]);

        float* o = out + p * 16129 + h * 127 + w0;

        #pragma unroll
        for (int k = 0; k < 4; k++) {
            // wires: 0=top-left, 1=top-right, 2=bottom-left, 3=bottom-right
            float C0 = Ct[k],     S0 = St[k];
            float C1 = Ct[k + 1], S1 = St[k + 1];
            float C2 = Cb[k],     S2 = Sb[k];
            float C3 = Cb[k + 1], S3 = Sb[k + 1];

            // level t3: r[a] = K0[a] + K1[a]*C3 + K2[a]*S3, a = t0*9+t1*3+t2
            float r[28];
            #pragma unroll
            for (int v = 0; v < 7; v++) {
                float4 k0 = sK4[v], k1 = sK4[7 + v], k2 = sK4[14 + v];
                r[4 * v + 0] = fmaf(k1.x, C3, fmaf(k2.x, S3, k0.x));
                r[4 * v + 1] = fmaf(k1.y, C3, fmaf(k2.y, S3, k0.y));
                r[4 * v + 2] = fmaf(k1.z, C3, fmaf(k2.z, S3, k0.z));
                r[4 * v + 3] = fmaf(k1.w, C3, fmaf(k2.w, S3, k0.w));
            }

            // level t2
            float r2[9];
            #pragma unroll
            for (int a = 0; a < 9; a++)
                r2[a] = fmaf(r[3 * a + 1], C2, fmaf(r[3 * a + 2], S2, r[3 * a]));

            // levels t1, t0
            float ra = fmaf(r2[1], C1, fmaf(r2[2], S1, r2[0]));
            float rb = fmaf(r2[4], C1, fmaf(r2[5], S1, r2[3]));
            float rc = fmaf(r2[7], C1, fmaf(r2[8], S1, r2[6]));
            float ev = fmaf(rb, C0, fmaf(rc, S0, ra));

            if (k < npix) o[k] = ev;
        }
    }
}

extern "C" void kernel_launch(void* const* d_in, const int* in_sizes, int n_in,
                              void* d_out, int out_size) {
    const float* x = (const float*)d_in[0];   // [32,3,128,128]
    const float* w = (const float*)d_in[1];   // [2,4,3]
    float* out = (float*)d_out;               // [32,3,127,127]

    const int nStrips = 96 * 127 * 32;        // 390144
    const int blocks  = 444;                  // one wave: 3 blocks/SM x 148 SMs
    qcl_fused_kernel<<<blocks, 256>>>(x, w, out, nStrips);
}